// round 15
// baseline (speedup 1.0000x reference)
#include <cuda_runtime.h>

#define NNODES 50000
#define NB 2
#define FDIM 128
#define EDGES_MAX 800000
#define NODES_PB 32
#define NBLOCKS ((NNODES + NODES_PB - 1) / NODES_PB)   // 1563
#define SCAN_BLOCKS ((NNODES + 255) / 256)             // 196

// Scratch: __device__ globals only
__device__ int g_deg[NNODES];
__device__ int g_rowstart[NNODES + 1];
__device__ int g_exloc[NNODES];
__device__ int g_bsum[SCAN_BLOCKS];
__device__ int g_ticket[EDGES_MAX];
__device__ int g_csr[EDGES_MAX];
__device__ unsigned g_whi[FDIM * FDIM];   // W split: tf32 hi bits
__device__ unsigned g_wlo[FDIM * FDIM];   // W split: tf32 lo (residual) bits

// ---------------------------------------------------------------------------
__device__ __forceinline__ void tf32split(float x, unsigned& hi, unsigned& lo) {
    asm("cvt.rna.tf32.f32 %0, %1;" : "=r"(hi) : "f"(x));
    float r = x - __uint_as_float(hi);
    asm("cvt.rna.tf32.f32 %0, %1;" : "=r"(lo) : "f"(r));
}

// W hi/lo split (16384 elems, runs once per call, ~2us)
__global__ void k_wsplit(const float* __restrict__ weight) {
    int i = blockIdx.x * blockDim.x + threadIdx.x;
    if (i < FDIM * FDIM) {
        unsigned hi, lo;
        tf32split(weight[i], hi, lo);
        g_whi[i] = hi;
        g_wlo[i] = lo;
    }
}

// ---------------------------------------------------------------------------
// edges int32 [E,2]; 2 edges per thread. Records per-edge arrival tickets.
__global__ void k_hist(const int4* __restrict__ edges2, int Epairs) {
    int i = blockIdx.x * blockDim.x + threadIdx.x;
    if (i < Epairs) {
        int4 e2 = edges2[i];
        int t0 = atomicAdd(&g_deg[e2.y], 1);
        int t1 = atomicAdd(&g_deg[e2.w], 1);
        *(int2*)&g_ticket[2 * i] = make_int2(t0, t1);
    }
}

__global__ void __launch_bounds__(256)
k_scan_local() {
    __shared__ int wsum[8];
    const int tid = threadIdx.x;
    const int i = blockIdx.x * 256 + tid;
    const int lane = tid & 31;
    const int wrp = tid >> 5;

    int val = (i < NNODES) ? g_deg[i] : 0;
    int incl = val;
    #pragma unroll
    for (int off = 1; off < 32; off <<= 1) {
        int v = __shfl_up_sync(0xffffffffu, incl, off);
        if (lane >= off) incl += v;
    }
    if (lane == 31) wsum[wrp] = incl;
    __syncthreads();
    if (wrp == 0) {
        int s = (lane < 8) ? wsum[lane] : 0;
        #pragma unroll
        for (int off = 1; off < 8; off <<= 1) {
            int v = __shfl_up_sync(0xffffffffu, s, off);
            if (lane >= off) s += v;
        }
        if (lane < 8) wsum[lane] = s;
    }
    __syncthreads();
    const int warpOff = (wrp == 0) ? 0 : wsum[wrp - 1];
    if (i < NNODES) g_exloc[i] = warpOff + incl - val;
    if (tid == 255) g_bsum[blockIdx.x] = warpOff + incl;
}

__global__ void __launch_bounds__(256)
k_scan_add() {
    __shared__ int blockOff;
    const int tid = threadIdx.x;
    const int bid = blockIdx.x;

    if (tid < 32) {
        int s = 0;
        for (int i = tid; i < bid; i += 32) s += g_bsum[i];
        int own = (bid == SCAN_BLOCKS - 1 && tid == 0)
                      ? g_bsum[SCAN_BLOCKS - 1] : 0;
        #pragma unroll
        for (int off = 16; off > 0; off >>= 1)
            s += __shfl_down_sync(0xffffffffu, s, off);
        if (tid == 0) {
            blockOff = s;
            if (bid == SCAN_BLOCKS - 1) g_rowstart[NNODES] = s + own;
        }
    }
    __syncthreads();

    const int i = bid * 256 + tid;
    if (i < NNODES) {
        g_rowstart[i] = g_exloc[i] + blockOff;
        g_deg[i] = 0;
    }
}

__global__ void k_fill(const int4* __restrict__ edges2, int Epairs) {
    int i = blockIdx.x * blockDim.x + threadIdx.x;
    if (i < Epairs) {
        int4 e2 = edges2[i];
        int2 t = *(const int2*)&g_ticket[2 * i];
        g_csr[g_rowstart[e2.y] + t.x] = e2.x;
        g_csr[g_rowstart[e2.w] + t.y] = e2.z;
    }
}

// ---------------------------------------------------------------------------
// m16n8k8 tf32 MMA, register fragments (PTX ISA layouts)
__device__ __forceinline__ void mma_tf32(float* c,
                                         unsigned a0, unsigned a1,
                                         unsigned a2, unsigned a3,
                                         unsigned b0, unsigned b1) {
    asm volatile(
        "mma.sync.aligned.m16n8k8.row.col.f32.tf32.tf32.f32 "
        "{%0,%1,%2,%3}, {%4,%5,%6,%7}, {%8,%9}, {%0,%1,%2,%3};"
        : "+f"(c[0]), "+f"(c[1]), "+f"(c[2]), "+f"(c[3])
        : "r"(a0), "r"(a1), "r"(a2), "r"(a3), "r"(b0), "r"(b1));
}

// ---------------------------------------------------------------------------
// Fused: gather 32 nodes x 2 batches -> As[64][132] fp32 rows
// (row = 2*nl + batch), then tf32x3 tensor-core GEMM 64x128x128 + bias + relu.
// Warp (wm = w&3, wn = w>>2): rows 16*wm..+16, cols 64*wn..+64.
#define AS_LD 132
#define WS_LD 136
#define SMEM_BYTES ((64 * AS_LD + 2 * 32 * WS_LD) * 4)   // 68608 B

__global__ void __launch_bounds__(256, 3)
k_fused(const float* __restrict__ nodes,
        const float* __restrict__ bias,
        float* __restrict__ out) {
    extern __shared__ float smem[];
    float* As = smem;                                   // 64 x 132
    unsigned* Wh = (unsigned*)(smem + 64 * AS_LD);      // 32 x 136
    unsigned* Wl = Wh + 32 * WS_LD;                     // 32 x 136

    const int tid = threadIdx.x;
    const int w = tid >> 5;
    const int lane = tid & 31;
    const int node0 = blockIdx.x * NODES_PB;

    // ---- phase 1: aggregation (both batches), MLP 4 — proven loop ----
    #pragma unroll 1
    for (int j = 0; j < 4; j++) {
        const int nl = w * 4 + j;            // local node 0..31
        const int n = node0 + nl;
        float4 acc0 = make_float4(0.f, 0.f, 0.f, 0.f);
        float4 acc1 = make_float4(0.f, 0.f, 0.f, 0.f);
        float scale = 0.0f;
        if (n < NNODES) {
            const int rs = g_rowstart[n];
            const int re = g_rowstart[n + 1];
            const float* nb0 = nodes + lane * 4;
            const float* nb1 = nodes + (size_t)NNODES * FDIM + lane * 4;
            int i = rs;
            for (; i + 2 <= re; i += 2) {
                int s0 = g_csr[i], s1 = g_csr[i + 1];
                float4 a = *(const float4*)(nb0 + (size_t)s0 * FDIM);
                float4 b = *(const float4*)(nb0 + (size_t)s1 * FDIM);
                float4 c = *(const float4*)(nb1 + (size_t)s0 * FDIM);
                float4 d = *(const float4*)(nb1 + (size_t)s1 * FDIM);
                acc0.x += a.x + b.x; acc0.y += a.y + b.y;
                acc0.z += a.z + b.z; acc0.w += a.w + b.w;
                acc1.x += c.x + d.x; acc1.y += c.y + d.y;
                acc1.z += c.z + d.z; acc1.w += c.w + d.w;
            }
            if (i < re) {
                int s0 = g_csr[i];
                float4 a = *(const float4*)(nb0 + (size_t)s0 * FDIM);
                float4 c = *(const float4*)(nb1 + (size_t)s0 * FDIM);
                acc0.x += a.x; acc0.y += a.y; acc0.z += a.z; acc0.w += a.w;
                acc1.x += c.x; acc1.y += c.y; acc1.z += c.z; acc1.w += c.w;
            }
            scale = 1.0f / (float)(re - rs + 1);
        }
        float4 r0 = make_float4(acc0.x * scale, acc0.y * scale,
                                acc0.z * scale, acc0.w * scale);
        float4 r1 = make_float4(acc1.x * scale, acc1.y * scale,
                                acc1.z * scale, acc1.w * scale);
        *(float4*)&As[(2 * nl) * AS_LD + lane * 4] = r0;      // batch 0 row
        *(float4*)&As[(2 * nl + 1) * AS_LD + lane * 4] = r1;  // batch 1 row
    }

    // ---- phase 2: tf32x3 MMA GEMM ----
    const int wm = w & 3;          // row tile: 16*wm
    const int wn = w >> 1 & ~0;    // placeholder (computed below properly)
    const int wcol = (w >> 2) * 64;  // col half: 0 or 64
    const int gid = lane >> 2;     // 0..7
    const int tig = lane & 3;      // 0..3

    float acc[8][4];
    #pragma unroll
    for (int nt = 0; nt < 8; nt++) {
        acc[nt][0] = 0.f; acc[nt][1] = 0.f;
        acc[nt][2] = 0.f; acc[nt][3] = 0.f;
    }

    #pragma unroll
    for (int kc = 0; kc < 4; kc++) {
        __syncthreads();   // kc=0: As ready; kc>0: prior W reads done
        // stage W k-chunk (hi+lo), padded rows
        {
            const uint4* sh = (const uint4*)(g_whi + kc * 4096);
            const uint4* sl = (const uint4*)(g_wlo + kc * 4096);
            #pragma unroll
            for (int i = 0; i < 4; i++) {
                int e = tid + i * 256;          // uint4 index
                int row = (4 * e) >> 7;         // /128
                int col = (4 * e) & 127;
                *(uint4*)&Wh[row * WS_LD + col] = sh[e];
                *(uint4*)&Wl[row * WS_LD + col] = sl[e];
            }
        }
        __syncthreads();

        #pragma unroll
        for (int ks = 0; ks < 4; ks++) {
            const int kb = kc * 32 + ks * 8;
            // A fragment (m16k8 row-major): a0=(r,c) a1=(r+8,c) a2=(r,c+4) a3=(r+8,c+4)
            const float a0r = As[(wm * 16 + gid) * AS_LD + kb + tig];
            const float a1r = As[(wm * 16 + gid + 8) * AS_LD + kb + tig];
            const float a2r = As[(wm * 16 + gid) * AS_LD + kb + tig + 4];
            const float a3r = As[(wm * 16 + gid + 8) * AS_LD + kb + tig + 4];
            unsigned ah0, ah1, ah2, ah3, al0, al1, al2, al3;
            tf32split(a0r, ah0, al0);
            tf32split(a1r, ah1, al1);
            tf32split(a2r, ah2, al2);
            tf32split(a3r, ah3, al3);

            const int kr = ks * 8 + tig;   // B frag k-row within chunk
            #pragma unroll
            for (int nt = 0; nt < 8; nt++) {
                const int nb = wcol + nt * 8 + gid;
                const unsigned bh0 = Wh[kr * WS_LD + nb];
                const unsigned bh1 = Wh[(kr + 4) * WS_LD + nb];
                const unsigned bl0 = Wl[kr * WS_LD + nb];
                const unsigned bl1 = Wl[(kr + 4) * WS_LD + nb];
                mma_tf32(acc[nt], ah0, ah1, ah2, ah3, bh0, bh1);  // hi*hi
                mma_tf32(acc[nt], ah0, ah1, ah2, ah3, bl0, bl1);  // hi*lo
                mma_tf32(acc[nt], al0, al1, al2, al3, bh0, bh1);  // lo*hi
            }
        }
    }

    // ---- epilogue: bias + relu, As row r -> batch=r&1, node=node0+(r>>1) ----
    const int rowA = wm * 16 + gid;
    const int rowB = rowA + 8;
    const int nodeA = node0 + (rowA >> 1);
    const int nodeB = node0 + (rowB >> 1);
    const size_t offA = ((size_t)(rowA & 1) * NNODES + nodeA) * FDIM;
    const size_t offB = ((size_t)(rowB & 1) * NNODES + nodeB) * FDIM;

    #pragma unroll
    for (int nt = 0; nt < 8; nt++) {
        const int col = wcol + nt * 8 + 2 * tig;
        const float2 bv = *(const float2*)&bias[col];
        if (nodeA < NNODES) {
            float2 o;
            o.x = fmaxf(acc[nt][0] + bv.x, 0.f);
            o.y = fmaxf(acc[nt][1] + bv.y, 0.f);
            *(float2*)&out[offA + col] = o;
        }
        if (nodeB < NNODES) {
            float2 o;
            o.x = fmaxf(acc[nt][2] + bv.x, 0.f);
            o.y = fmaxf(acc[nt][3] + bv.y, 0.f);
            *(float2*)&out[offB + col] = o;
        }
    }
}

// ---------------------------------------------------------------------------
extern "C" void kernel_launch(void* const* d_in, const int* in_sizes, int n_in,
                              void* d_out, int out_size) {
    const float* nodes = (const float*)d_in[0];
    const int4* edges2 = (const int4*)d_in[1];   // int32 [E,2]
    const float* weight = (const float*)d_in[2];
    const float* bias = (const float*)d_in[3];
    float* out = (float*)d_out;

    int E = in_sizes[1] / 2;
    if (E > EDGES_MAX) E = EDGES_MAX;
    int Epairs = E / 2;

    cudaFuncSetAttribute(k_fused, cudaFuncAttributeMaxDynamicSharedMemorySize,
                         SMEM_BYTES);

    k_wsplit<<<(FDIM * FDIM + 255) / 256, 256>>>(weight);
    k_hist<<<(Epairs + 255) / 256, 256>>>(edges2, Epairs);
    k_scan_local<<<SCAN_BLOCKS, 256>>>();
    k_scan_add<<<SCAN_BLOCKS, 256>>>();
    k_fill<<<(Epairs + 255) / 256, 256>>>(edges2, Epairs);
    k_fused<<<NBLOCKS, 256, SMEM_BYTES>>>(nodes, bias, out);
}

// round 16
// speedup vs baseline: 1.0571x; 1.0571x over previous
#include <cuda_runtime.h>

#define NNODES 50000
#define NB 2
#define FDIM 128
#define EDGES_MAX 800000
#define NODES_PB 32
#define NBLOCKS ((NNODES + NODES_PB - 1) / NODES_PB)   // 1563
#define SCAN_BLOCKS ((NNODES + 255) / 256)             // 196

// Scratch: __device__ globals only (zero-initialized at module load; the
// scan pipeline self-clears g_deg each call so graph replays are identical)
__device__ int g_deg[NNODES];
__device__ int g_rowstart[NNODES + 1];
__device__ int g_exloc[NNODES];
__device__ int g_bsum[SCAN_BLOCKS];
__device__ int g_ticket[EDGES_MAX];    // arrival index within dst bucket
__device__ int g_csr[EDGES_MAX];

// ---------------------------------------------------------------------------
// edges int32 [E,2]; 2 edges per thread. Records per-edge arrival tickets.
__global__ void k_hist(const int4* __restrict__ edges2, int Epairs) {
    int i = blockIdx.x * blockDim.x + threadIdx.x;
    if (i < Epairs) {
        int4 e2 = edges2[i];
        int t0 = atomicAdd(&g_deg[e2.y], 1);
        int t1 = atomicAdd(&g_deg[e2.w], 1);
        *(int2*)&g_ticket[2 * i] = make_int2(t0, t1);   // coalesced
    }
}

// A: per-block exclusive scan of g_deg (coalesced), block sums to g_bsum
__global__ void __launch_bounds__(256)
k_scan_local() {
    __shared__ int wsum[8];
    const int tid = threadIdx.x;
    const int i = blockIdx.x * 256 + tid;
    const int lane = tid & 31;
    const int wrp = tid >> 5;

    int val = (i < NNODES) ? g_deg[i] : 0;
    int incl = val;
    #pragma unroll
    for (int off = 1; off < 32; off <<= 1) {
        int v = __shfl_up_sync(0xffffffffu, incl, off);
        if (lane >= off) incl += v;
    }
    if (lane == 31) wsum[wrp] = incl;
    __syncthreads();
    if (wrp == 0) {
        int s = (lane < 8) ? wsum[lane] : 0;
        #pragma unroll
        for (int off = 1; off < 8; off <<= 1) {
            int v = __shfl_up_sync(0xffffffffu, s, off);
            if (lane >= off) s += v;
        }
        if (lane < 8) wsum[lane] = s;
    }
    __syncthreads();
    const int warpOff = (wrp == 0) ? 0 : wsum[wrp - 1];
    if (i < NNODES) g_exloc[i] = warpOff + incl - val;
    if (tid == 255) g_bsum[blockIdx.x] = warpOff + incl;
}

// B (merged): block computes its bsum-prefix with warp 0, then distributes
// rowstart and self-clears g_deg. Last block writes the grand total.
__global__ void __launch_bounds__(256)
k_scan_add() {
    __shared__ int blockOff;
    const int tid = threadIdx.x;
    const int bid = blockIdx.x;

    if (tid < 32) {
        int s = 0;
        for (int i = tid; i < bid; i += 32) s += g_bsum[i];
        int own = (bid == SCAN_BLOCKS - 1 && tid == 0)
                      ? g_bsum[SCAN_BLOCKS - 1] : 0;
        #pragma unroll
        for (int off = 16; off > 0; off >>= 1)
            s += __shfl_down_sync(0xffffffffu, s, off);
        if (tid == 0) {
            blockOff = s;
            if (bid == SCAN_BLOCKS - 1) g_rowstart[NNODES] = s + own;
        }
    }
    __syncthreads();

    const int i = bid * 256 + tid;
    if (i < NNODES) {
        g_rowstart[i] = g_exloc[i] + blockOff;
        g_deg[i] = 0;
    }
}

// Atomic-free CSR fill: slot = rowstart[dst] + ticket (precomputed in hist)
__global__ void k_fill(const int4* __restrict__ edges2, int Epairs) {
    int i = blockIdx.x * blockDim.x + threadIdx.x;
    if (i < Epairs) {
        int4 e2 = edges2[i];
        int2 t = *(const int2*)&g_ticket[2 * i];
        g_csr[g_rowstart[e2.y] + t.x] = e2.x;
        g_csr[g_rowstart[e2.w] + t.y] = e2.z;
    }
}

// ---------------------------------------------------------------------------
// Packed f32x2 helpers (FFMA2 path — ptxas won't auto-fuse)
__device__ __forceinline__ unsigned long long pack2(float x, float y) {
    unsigned long long r;
    asm("mov.b64 %0, {%1, %2};" : "=l"(r) : "f"(x), "f"(y));
    return r;
}
__device__ __forceinline__ void unpack2(unsigned long long v, float& x, float& y) {
    asm("mov.b64 {%0, %1}, %2;" : "=f"(x), "=f"(y) : "l"(v));
}
__device__ __forceinline__ void fma2(unsigned long long& d,
                                     unsigned long long a,
                                     unsigned long long b) {
    asm("fma.rn.f32x2 %0, %1, %2, %0;" : "+l"(d) : "l"(a), "l"(b));
}

// ---------------------------------------------------------------------------
// Fused (R13 decomposition, 4 blocks/SM): 256 threads, 8 warps,
// 32 nodes x both batches per block, 64-reg cap -> 32 warps/SM (50% occ).
// Inner-loop live regs ~52 (32 acc + 8 W packs + ap + control) -> cap should
// compile spill-free in the hot loops; the extra 8 warps/SM cover gather
// L2 latency (fused showed occ 34.5%, no saturated pipe).
__global__ void __launch_bounds__(256, 4)
k_fused(const float* __restrict__ nodes,
        const float* __restrict__ weight,
        const float* __restrict__ bias,
        float* __restrict__ out) {
    __shared__ float2 As2[NODES_PB][FDIM];   // 32KB {batch0, batch1}
    __shared__ float Ws[32][FDIM];           // 16KB (one k-quarter of W)

    const int tid = threadIdx.x;
    const int w = tid >> 5;
    const int lane = tid & 31;
    const int node0 = blockIdx.x * NODES_PB;

    // ---- phase 1: aggregation (both batches), MLP 4 ----
    #pragma unroll 1
    for (int j = 0; j < 4; j++) {
        const int nl = w * 4 + j;            // local node 0..31
        const int n = node0 + nl;
        float4 acc0 = make_float4(0.f, 0.f, 0.f, 0.f);
        float4 acc1 = make_float4(0.f, 0.f, 0.f, 0.f);
        float scale = 0.0f;
        if (n < NNODES) {
            const int rs = g_rowstart[n];
            const int re = g_rowstart[n + 1];
            const float* nb0 = nodes + lane * 4;
            const float* nb1 = nodes + (size_t)NNODES * FDIM + lane * 4;
            int i = rs;
            for (; i + 2 <= re; i += 2) {
                int s0 = g_csr[i], s1 = g_csr[i + 1];
                float4 a = *(const float4*)(nb0 + (size_t)s0 * FDIM);
                float4 b = *(const float4*)(nb0 + (size_t)s1 * FDIM);
                float4 c = *(const float4*)(nb1 + (size_t)s0 * FDIM);
                float4 d = *(const float4*)(nb1 + (size_t)s1 * FDIM);
                acc0.x += a.x + b.x; acc0.y += a.y + b.y;
                acc0.z += a.z + b.z; acc0.w += a.w + b.w;
                acc1.x += c.x + d.x; acc1.y += c.y + d.y;
                acc1.z += c.z + d.z; acc1.w += c.w + d.w;
            }
            if (i < re) {
                int s0 = g_csr[i];
                float4 a = *(const float4*)(nb0 + (size_t)s0 * FDIM);
                float4 c = *(const float4*)(nb1 + (size_t)s0 * FDIM);
                acc0.x += a.x; acc0.y += a.y; acc0.z += a.z; acc0.w += a.w;
                acc1.x += c.x; acc1.y += c.y; acc1.z += c.z; acc1.w += c.w;
            }
            scale = 1.0f / (float)(re - rs + 1);
        }
        float4 lo = make_float4(acc0.x * scale, acc1.x * scale,
                                acc0.y * scale, acc1.y * scale);
        float4 hi = make_float4(acc0.z * scale, acc1.z * scale,
                                acc0.w * scale, acc1.w * scale);
        *(float4*)&As2[nl][lane * 4] = lo;
        *(float4*)&As2[nl][lane * 4 + 2] = hi;
    }

    // ---- phase 2: GEMM ----
    const int colg = tid & 31;    // cols 4*colg .. +4
    const int nodeg = tid >> 5;   // local nodes 4*nodeg .. +4

    const float4 b4 = *(const float4*)(bias + colg * 4);
    unsigned long long acc[4][4];   // [node][col], packed {b0,b1}
    #pragma unroll
    for (int j = 0; j < 4; j++) {
        acc[j][0] = pack2(b4.x, b4.x);
        acc[j][1] = pack2(b4.y, b4.y);
        acc[j][2] = pack2(b4.z, b4.z);
        acc[j][3] = pack2(b4.w, b4.w);
    }

    const float4* w4g = (const float4*)weight;
    #pragma unroll
    for (int kq = 0; kq < 4; kq++) {
        __syncthreads();   // kq=0: As2 ready; kq>0: prior Ws reads done
        #pragma unroll
        for (int i = 0; i < 4; i++)
            ((float4*)Ws)[tid + i * 256] = w4g[kq * 1024 + tid + i * 256];
        __syncthreads();

        #pragma unroll 4
        for (int k = 0; k < 32; k++) {
            const float4 wv = *(const float4*)&Ws[k][colg * 4];
            const unsigned long long w0 = pack2(wv.x, wv.x);
            const unsigned long long w1 = pack2(wv.y, wv.y);
            const unsigned long long w2 = pack2(wv.z, wv.z);
            const unsigned long long w3 = pack2(wv.w, wv.w);
            #pragma unroll
            for (int j = 0; j < 4; j++) {
                const unsigned long long ap =
                    *(const unsigned long long*)&As2[nodeg * 4 + j][kq * 32 + k];
                fma2(acc[j][0], w0, ap);
                fma2(acc[j][1], w1, ap);
                fma2(acc[j][2], w2, ap);
                fma2(acc[j][3], w3, ap);
            }
        }
    }

    // ---- store with relu (unpack batch lanes) ----
    #pragma unroll
    for (int j = 0; j < 4; j++) {
        const int n = node0 + nodeg * 4 + j;
        if (n < NNODES) {
            float x0, y0, x1, y1, x2, y2, x3, y3;
            unpack2(acc[j][0], x0, y0);
            unpack2(acc[j][1], x1, y1);
            unpack2(acc[j][2], x2, y2);
            unpack2(acc[j][3], x3, y3);
            float4 o0 = make_float4(fmaxf(x0, 0.f), fmaxf(x1, 0.f),
                                    fmaxf(x2, 0.f), fmaxf(x3, 0.f));
            float4 o1 = make_float4(fmaxf(y0, 0.f), fmaxf(y1, 0.f),
                                    fmaxf(y2, 0.f), fmaxf(y3, 0.f));
            *(float4*)(out + (size_t)n * FDIM + colg * 4) = o0;
            *(float4*)(out + (size_t)(NNODES + n) * FDIM + colg * 4) = o1;
        }
    }
}

// ---------------------------------------------------------------------------
extern "C" void kernel_launch(void* const* d_in, const int* in_sizes, int n_in,
                              void* d_out, int out_size) {
    const float* nodes = (const float*)d_in[0];
    const int4* edges2 = (const int4*)d_in[1];   // int32 [E,2]
    const float* weight = (const float*)d_in[2];
    const float* bias = (const float*)d_in[3];
    float* out = (float*)d_out;

    int E = in_sizes[1] / 2;
    if (E > EDGES_MAX) E = EDGES_MAX;
    int Epairs = E / 2;

    k_hist<<<(Epairs + 255) / 256, 256>>>(edges2, Epairs);
    k_scan_local<<<SCAN_BLOCKS, 256>>>();
    k_scan_add<<<SCAN_BLOCKS, 256>>>();
    k_fill<<<(Epairs + 255) / 256, 256>>>(edges2, Epairs);
    k_fused<<<NBLOCKS, 256>>>(nodes, weight, bias, out);
}

// round 17
// speedup vs baseline: 1.3118x; 1.2409x over previous
#include <cuda_runtime.h>

#define NNODES 50000
#define NB 2
#define FDIM 128
#define EDGES_MAX 800000
#define NODES_PB 32
#define NBLOCKS ((NNODES + NODES_PB - 1) / NODES_PB)   // 1563
#define SCAN_BLOCKS ((NNODES + 255) / 256)             // 196

// Scratch: __device__ globals only
__device__ int g_deg[NNODES];
__device__ int g_rowstart[NNODES + 1];
__device__ int g_exloc[NNODES];
__device__ int g_bsum[SCAN_BLOCKS];
__device__ int g_ticket[EDGES_MAX];
__device__ int g_csr[EDGES_MAX];
__device__ unsigned g_wtf[FDIM * FDIM];   // W pre-converted to tf32 bits

// ---------------------------------------------------------------------------
__device__ __forceinline__ unsigned to_tf32(float x) {
    unsigned r;
    asm("cvt.rna.tf32.f32 %0, %1;" : "=r"(r) : "f"(x));
    return r;
}

__global__ void k_wconv(const float* __restrict__ weight) {
    int i = blockIdx.x * blockDim.x + threadIdx.x;
    if (i < FDIM * FDIM) g_wtf[i] = to_tf32(weight[i]);
}

// ---------------------------------------------------------------------------
// edges int32 [E,2]; 2 edges per thread. Records per-edge arrival tickets.
__global__ void k_hist(const int4* __restrict__ edges2, int Epairs) {
    int i = blockIdx.x * blockDim.x + threadIdx.x;
    if (i < Epairs) {
        int4 e2 = edges2[i];
        int t0 = atomicAdd(&g_deg[e2.y], 1);
        int t1 = atomicAdd(&g_deg[e2.w], 1);
        *(int2*)&g_ticket[2 * i] = make_int2(t0, t1);
    }
}

__global__ void __launch_bounds__(256)
k_scan_local() {
    __shared__ int wsum[8];
    const int tid = threadIdx.x;
    const int i = blockIdx.x * 256 + tid;
    const int lane = tid & 31;
    const int wrp = tid >> 5;

    int val = (i < NNODES) ? g_deg[i] : 0;
    int incl = val;
    #pragma unroll
    for (int off = 1; off < 32; off <<= 1) {
        int v = __shfl_up_sync(0xffffffffu, incl, off);
        if (lane >= off) incl += v;
    }
    if (lane == 31) wsum[wrp] = incl;
    __syncthreads();
    if (wrp == 0) {
        int s = (lane < 8) ? wsum[lane] : 0;
        #pragma unroll
        for (int off = 1; off < 8; off <<= 1) {
            int v = __shfl_up_sync(0xffffffffu, s, off);
            if (lane >= off) s += v;
        }
        if (lane < 8) wsum[lane] = s;
    }
    __syncthreads();
    const int warpOff = (wrp == 0) ? 0 : wsum[wrp - 1];
    if (i < NNODES) g_exloc[i] = warpOff + incl - val;
    if (tid == 255) g_bsum[blockIdx.x] = warpOff + incl;
}

__global__ void __launch_bounds__(256)
k_scan_add() {
    __shared__ int blockOff;
    const int tid = threadIdx.x;
    const int bid = blockIdx.x;

    if (tid < 32) {
        int s = 0;
        for (int i = tid; i < bid; i += 32) s += g_bsum[i];
        int own = (bid == SCAN_BLOCKS - 1 && tid == 0)
                      ? g_bsum[SCAN_BLOCKS - 1] : 0;
        #pragma unroll
        for (int off = 16; off > 0; off >>= 1)
            s += __shfl_down_sync(0xffffffffu, s, off);
        if (tid == 0) {
            blockOff = s;
            if (bid == SCAN_BLOCKS - 1) g_rowstart[NNODES] = s + own;
        }
    }
    __syncthreads();

    const int i = bid * 256 + tid;
    if (i < NNODES) {
        g_rowstart[i] = g_exloc[i] + blockOff;
        g_deg[i] = 0;
    }
}

__global__ void k_fill(const int4* __restrict__ edges2, int Epairs) {
    int i = blockIdx.x * blockDim.x + threadIdx.x;
    if (i < Epairs) {
        int4 e2 = edges2[i];
        int2 t = *(const int2*)&g_ticket[2 * i];
        g_csr[g_rowstart[e2.y] + t.x] = e2.x;
        g_csr[g_rowstart[e2.w] + t.y] = e2.z;
    }
}

// ---------------------------------------------------------------------------
// m16n8k8 tf32 MMA (fragment layout verified correct in R15)
__device__ __forceinline__ void mma_tf32(float* c,
                                         unsigned a0, unsigned a1,
                                         unsigned a2, unsigned a3,
                                         unsigned b0, unsigned b1) {
    asm volatile(
        "mma.sync.aligned.m16n8k8.row.col.f32.tf32.tf32.f32 "
        "{%0,%1,%2,%3}, {%4,%5,%6,%7}, {%8,%9}, {%0,%1,%2,%3};"
        : "+f"(c[0]), "+f"(c[1]), "+f"(c[2]), "+f"(c[3])
        : "r"(a0), "r"(a1), "r"(a2), "r"(a3), "r"(b0), "r"(b1));
}

// ---------------------------------------------------------------------------
// Fused: gather 32 nodes x 2 batches -> As[64][132] fp32 (row = 2*nl+batch),
// then SINGLE-PASS tf32 MMA GEMM 64x128x128 + bias + relu.
#define AS_LD 132
#define WS_LD 136
#define SMEM_BYTES ((64 * AS_LD + 32 * WS_LD) * 4)   // 51200 B

__global__ void __launch_bounds__(256, 3)
k_fused(const float* __restrict__ nodes,
        const float* __restrict__ bias,
        float* __restrict__ out) {
    extern __shared__ float smem[];
    float* As = smem;                                   // 64 x 132
    unsigned* Wh = (unsigned*)(smem + 64 * AS_LD);      // 32 x 136 (tf32)

    const int tid = threadIdx.x;
    const int w = tid >> 5;
    const int lane = tid & 31;
    const int node0 = blockIdx.x * NODES_PB;

    // ---- phase 1: aggregation (both batches), MLP 4 — proven loop ----
    #pragma unroll 1
    for (int j = 0; j < 4; j++) {
        const int nl = w * 4 + j;
        const int n = node0 + nl;
        float4 acc0 = make_float4(0.f, 0.f, 0.f, 0.f);
        float4 acc1 = make_float4(0.f, 0.f, 0.f, 0.f);
        float scale = 0.0f;
        if (n < NNODES) {
            const int rs = g_rowstart[n];
            const int re = g_rowstart[n + 1];
            const float* nb0 = nodes + lane * 4;
            const float* nb1 = nodes + (size_t)NNODES * FDIM + lane * 4;
            int i = rs;
            for (; i + 2 <= re; i += 2) {
                int s0 = g_csr[i], s1 = g_csr[i + 1];
                float4 a = *(const float4*)(nb0 + (size_t)s0 * FDIM);
                float4 b = *(const float4*)(nb0 + (size_t)s1 * FDIM);
                float4 c = *(const float4*)(nb1 + (size_t)s0 * FDIM);
                float4 d = *(const float4*)(nb1 + (size_t)s1 * FDIM);
                acc0.x += a.x + b.x; acc0.y += a.y + b.y;
                acc0.z += a.z + b.z; acc0.w += a.w + b.w;
                acc1.x += c.x + d.x; acc1.y += c.y + d.y;
                acc1.z += c.z + d.z; acc1.w += c.w + d.w;
            }
            if (i < re) {
                int s0 = g_csr[i];
                float4 a = *(const float4*)(nb0 + (size_t)s0 * FDIM);
                float4 c = *(const float4*)(nb1 + (size_t)s0 * FDIM);
                acc0.x += a.x; acc0.y += a.y; acc0.z += a.z; acc0.w += a.w;
                acc1.x += c.x; acc1.y += c.y; acc1.z += c.z; acc1.w += c.w;
            }
            scale = 1.0f / (float)(re - rs + 1);
        }
        float4 r0 = make_float4(acc0.x * scale, acc0.y * scale,
                                acc0.z * scale, acc0.w * scale);
        float4 r1 = make_float4(acc1.x * scale, acc1.y * scale,
                                acc1.z * scale, acc1.w * scale);
        *(float4*)&As[(2 * nl) * AS_LD + lane * 4] = r0;      // batch 0 row
        *(float4*)&As[(2 * nl + 1) * AS_LD + lane * 4] = r1;  // batch 1 row
    }

    // ---- phase 2: single-pass tf32 MMA GEMM ----
    const int wm = w & 3;            // row tile: 16*wm
    const int wcol = (w >> 2) * 64;  // col half: 0 or 64
    const int gid = lane >> 2;       // 0..7
    const int tig = lane & 3;        // 0..3

    float acc[8][4];
    #pragma unroll
    for (int nt = 0; nt < 8; nt++) {
        acc[nt][0] = 0.f; acc[nt][1] = 0.f;
        acc[nt][2] = 0.f; acc[nt][3] = 0.f;
    }

    #pragma unroll
    for (int kc = 0; kc < 4; kc++) {
        __syncthreads();   // kc=0: As ready; kc>0: prior W reads done
        // stage W tf32 k-chunk (padded rows, conflict-free layout)
        {
            const uint4* sh = (const uint4*)(g_wtf + kc * 4096);
            #pragma unroll
            for (int i = 0; i < 4; i++) {
                int e = tid + i * 256;          // uint4 index (1024 total)
                int row = (4 * e) >> 7;
                int col = (4 * e) & 127;
                *(uint4*)&Wh[row * WS_LD + col] = sh[e];
            }
        }
        __syncthreads();

        #pragma unroll
        for (int ks = 0; ks < 4; ks++) {
            const int kb = kc * 32 + ks * 8;
            // A fragment (m16k8 row-major) — verified layout
            const unsigned a0 = to_tf32(As[(wm * 16 + gid) * AS_LD + kb + tig]);
            const unsigned a1 = to_tf32(As[(wm * 16 + gid + 8) * AS_LD + kb + tig]);
            const unsigned a2 = to_tf32(As[(wm * 16 + gid) * AS_LD + kb + tig + 4]);
            const unsigned a3 = to_tf32(As[(wm * 16 + gid + 8) * AS_LD + kb + tig + 4]);

            const int kr = ks * 8 + tig;   // B frag k-row within chunk
            #pragma unroll
            for (int nt = 0; nt < 8; nt++) {
                const int nb = wcol + nt * 8 + gid;
                const unsigned b0 = Wh[kr * WS_LD + nb];
                const unsigned b1 = Wh[(kr + 4) * WS_LD + nb];
                mma_tf32(acc[nt], a0, a1, a2, a3, b0, b1);
            }
        }
    }

    // ---- epilogue (verified in R15): bias + relu ----
    const int rowA = wm * 16 + gid;
    const int rowB = rowA + 8;
    const int nodeA = node0 + (rowA >> 1);
    const int nodeB = node0 + (rowB >> 1);
    const size_t offA = ((size_t)(rowA & 1) * NNODES + nodeA) * FDIM;
    const size_t offB = ((size_t)(rowB & 1) * NNODES + nodeB) * FDIM;

    #pragma unroll
    for (int nt = 0; nt < 8; nt++) {
        const int col = wcol + nt * 8 + 2 * tig;
        const float2 bv = *(const float2*)&bias[col];
        if (nodeA < NNODES) {
            float2 o;
            o.x = fmaxf(acc[nt][0] + bv.x, 0.f);
            o.y = fmaxf(acc[nt][1] + bv.y, 0.f);
            *(float2*)&out[offA + col] = o;
        }
        if (nodeB < NNODES) {
            float2 o;
            o.x = fmaxf(acc[nt][2] + bv.x, 0.f);
            o.y = fmaxf(acc[nt][3] + bv.y, 0.f);
            *(float2*)&out[offB + col] = o;
        }
    }
}

// ---------------------------------------------------------------------------
extern "C" void kernel_launch(void* const* d_in, const int* in_sizes, int n_in,
                              void* d_out, int out_size) {
    const float* nodes = (const float*)d_in[0];
    const int4* edges2 = (const int4*)d_in[1];   // int32 [E,2]
    const float* weight = (const float*)d_in[2];
    const float* bias = (const float*)d_in[3];
    float* out = (float*)d_out;

    int E = in_sizes[1] / 2;
    if (E > EDGES_MAX) E = EDGES_MAX;
    int Epairs = E / 2;

    cudaFuncSetAttribute(k_fused, cudaFuncAttributeMaxDynamicSharedMemorySize,
                         SMEM_BYTES);

    k_wconv<<<(FDIM * FDIM + 255) / 256, 256>>>(weight);
    k_hist<<<(Epairs + 255) / 256, 256>>>(edges2, Epairs);
    k_scan_local<<<SCAN_BLOCKS, 256>>>();
    k_scan_add<<<SCAN_BLOCKS, 256>>>();
    k_fill<<<(Epairs + 255) / 256, 256>>>(edges2, Epairs);
    k_fused<<<NBLOCKS, 256, SMEM_BYTES>>>(nodes, bias, out);
}